// round 15
// baseline (speedup 1.0000x reference)
#include <cuda_runtime.h>
#include <cstdint>

#define N_NODES   100000
#define N_REL     8
#define IN_FEATS  64
#define HD        128
#define N_EDGES   800000
#define NEG_SLOPE 0.2f

#define EPB_HIST  1024
#define NBLK_HIST ((N_EDGES + EPB_HIST - 1) / EPB_HIST)   // 782
#define NB_D      ((N_NODES + 1023) / 1024)               // 98

#define NQUAD 3                 // warp quads per 384-thread block
#define CH    9                 // tiles per work-steal chunk (3 per quad)

typedef unsigned long long u64;
typedef unsigned int u32;

// ---------------- scratch ---------------------------------------------------
__device__ float g_p[N_EDGES * 4];       // exp(score), stored in DST order
__device__ int   g_edpos[N_EDGES];       // dst-order slot of each rel-sorted edge
__device__ int   g_srcr[N_EDGES];        // src node id, relation order
__device__ int   g_nidr[N_EDGES];        // nid node id, relation order
__device__ int   g_srcd[N_EDGES];        // src node id, dst order
__device__ int   g_relcnt[8];            // zero-init; re-zeroed by k_scan
__device__ int   g_relcur[8];
__device__ int   g_roff[9];
__device__ int   g_woff[9];              // 32-edge tile offsets per relation
__device__ int   g_choff[9];             // chunk offsets per relation
__device__ int   g_chunkcur;             // work-steal counter (reset by k_scan)
__device__ int   g_dstcnt[N_NODES];      // zero-init; re-zeroed by k_agg
__device__ int   g_rowoff[N_NODES + 1];
__device__ int   g_dstcur[N_NODES];
__device__ int   g_agg_v[NB_D];
__device__ int   g_agg_f[NB_D];          // zero-init; re-zeroed by k_agg
__device__ u32   g_wpk[8][2][4096];      // pre-packed bf16 weight fragments
__device__ float g_bs[8][128];           // bias sums
__device__ float2 g_at[8][128];          // (attn, -0.8*attn)

// ---------------- helpers ---------------------------------------------------
__device__ __forceinline__ long long ldidx(const void* p, int i, int is32) {
    return is32 ? (long long)((const int*)p)[i] : ((const long long*)p)[i];
}
// pack two floats -> bf16x2 (lo in low 16 bits)
__device__ __forceinline__ u32 bf2(float lo, float hi) {
    u32 r; asm("cvt.rn.bf16x2.f32 %0, %1, %2;" : "=r"(r) : "f"(hi), "f"(lo)); return r;
}
__device__ __forceinline__ void mma16(float* d, u32 a0, u32 a1, u32 a2, u32 a3,
                                      u32 b0, u32 b1) {
    asm volatile(
        "mma.sync.aligned.m16n8k16.row.col.f32.bf16.bf16.f32 "
        "{%0,%1,%2,%3}, {%4,%5,%6,%7}, {%8,%9}, {%0,%1,%2,%3};"
        : "+f"(d[0]), "+f"(d[1]), "+f"(d[2]), "+f"(d[3])
        : "r"(a0), "r"(a1), "r"(a2), "r"(a3), "r"(b0), "r"(b1));
}
__device__ __forceinline__ void barq(int id) {
    asm volatile("bar.sync %0, 128;" :: "r"(id) : "memory");
}
__device__ __forceinline__ int detect32(const void* p) {
    const long long* q = (const long long*)p;
    int bad = 0;
    #pragma unroll
    for (int j = 0; j < 16; j++) {
        long long v = q[j];
        if (v < 0 || v >= N_NODES) bad = 1;
    }
    return bad;
}

// ---------------- kernel 1: histogram + one-time weight pre-pack ------------
__global__ void k_hist(const void* __restrict__ rtp, const void* __restrict__ dstp,
                       const float* __restrict__ Wsrc, const float* __restrict__ Bsrc,
                       const float* __restrict__ Wqual, const float* __restrict__ Bqual,
                       const float* __restrict__ attn) {
    __shared__ int cnt[8];
    __shared__ int s_is32;
    int tid = threadIdx.x;
    if (tid < 8) cnt[tid] = 0;
    if (tid == 0) s_is32 = detect32(dstp);
    __syncthreads();
    const int is32 = s_is32;

    // blocks 0..127: pack weight fragments (one thread per fragment slot)
    int gidx = blockIdx.x * 256 + tid;
    if (gidx < 8 * 4096) {
        int idx = gidx & 4095;
        int r   = gidx >> 12;
        int half = idx & 1;
        int ln   = (idx >> 1) & 31;
        int nt   = (idx >> 6) & 15;
        int ks   = idx >> 10;
        int k = 16 * ks + 2 * (ln & 3) + 8 * half;
        int n = 8 * nt + (ln >> 2);
        const float* w0 = &Wsrc [(r * 64 + k) * 128 + n];
        const float* w1 = &Wqual[(r * 64 + k) * 128 + n];
        g_wpk[r][0][idx] = bf2(w0[0], w0[128]);
        g_wpk[r][1][idx] = bf2(w1[0], w1[128]);
    }
    if (gidx < 8 * 128) {
        int r = gidx >> 7, c = gidx & 127;
        g_bs[r][c] = Bsrc[r * 128 + c] + Bqual[r * 128 + c];
        float a = attn[r * 128 + c];
        g_at[r][c] = make_float2(a, -0.8f * a);
    }

    int base = blockIdx.x * EPB_HIST;
    for (int i = tid; i < EPB_HIST; i += 256) {
        int e = base + i;
        if (e < N_EDGES) {
            atomicAdd(&cnt[(int)ldidx(rtp, e, is32)], 1);
            atomicAdd(&g_dstcnt[(int)ldidx(dstp, e, is32)], 1);
        }
    }
    __syncthreads();
    if (tid < 8) atomicAdd(&g_relcnt[tid], cnt[tid]);
}

// ---------------- kernel 2: single-launch dst scan (decoupled lookback) -----
__global__ void __launch_bounds__(1024) k_scan() {
    __shared__ int ws[32];
    __shared__ int s_pred;
    int t = threadIdx.x, b = blockIdx.x;
    int i = b * 1024 + t;
    int v = (i < N_NODES) ? g_dstcnt[i] : 0;
    int lane = t & 31, w = t >> 5;
    int x = v;
    #pragma unroll
    for (int o = 1; o < 32; o <<= 1) {
        int y = __shfl_up_sync(0xffffffffu, x, o);
        if (lane >= o) x += y;
    }
    if (lane == 31) ws[w] = x;
    __syncthreads();
    if (t < 32) {
        int y = ws[t];
        #pragma unroll
        for (int o = 1; o < 32; o <<= 1) {
            int z = __shfl_up_sync(0xffffffffu, y, o);
            if (t >= o) y += z;
        }
        ws[t] = y;
    }
    __syncthreads();
    int excl = x - v + (w ? ws[w - 1] : 0);
    int btot = ws[31];
    if (t == 0) {
        s_pred = 0;
        g_agg_v[b] = btot;
        __threadfence();
        atomicExch(&g_agg_f[b], 1);
    }
    __syncthreads();
    if (t < b) {
        while (atomicAdd(&g_agg_f[t], 0) == 0) {}
        atomicAdd(&s_pred, atomicAdd(&g_agg_v[t], 0));
    }
    __syncthreads();
    int base = s_pred;
    if (i < N_NODES) {
        int val = base + excl;
        g_rowoff[i] = val;
        g_dstcur[i] = val;
    }
    if (b == 0 && t == 0) {
        int ro = 0, wo = 0, co = 0;
        for (int r = 0; r < 8; r++) {
            int c = g_relcnt[r];
            int tiles = (c + 31) / 32;
            g_roff[r] = ro; g_relcur[r] = ro; g_woff[r] = wo; g_choff[r] = co;
            ro += c; wo += tiles; co += (tiles + CH - 1) / CH;
            g_relcnt[r] = 0;
        }
        g_roff[8] = ro; g_woff[8] = wo; g_choff[8] = co;
        g_rowoff[N_NODES] = N_EDGES;
        g_chunkcur = 0;                       // reset work-steal counter
    }
}

// ---------------- kernel 3: fused scatter (rel ids + dst slots) -------------
__global__ void k_scatter(const void* __restrict__ rtp, const void* __restrict__ dstp,
                          const void* __restrict__ srcp, const void* __restrict__ nidp) {
    __shared__ int cnt[8], base[8];
    __shared__ int s_is32;
    int tid = threadIdx.x;
    if (tid < 8) cnt[tid] = 0;
    if (tid == 0) s_is32 = detect32(dstp);
    __syncthreads();
    const int is32 = s_is32;
    int b0 = blockIdx.x * EPB_HIST;
    int rloc[4], dloc[4], sloc[4], nloc[4];
    #pragma unroll
    for (int c = 0; c < 4; c++) {
        int e = b0 + c * 256 + tid;
        rloc[c] = -1;
        if (e < N_EDGES) {
            rloc[c] = (int)ldidx(rtp, e, is32);
            atomicAdd(&cnt[rloc[c]], 1);
            int d = (int)ldidx(dstp, e, is32);
            int s = (int)ldidx(srcp, e, is32);
            int q = (int)ldidx(nidp, e, is32);
            int pos = atomicAdd(&g_dstcur[d], 1);
            dloc[c] = pos; sloc[c] = s; nloc[c] = q;
            g_srcd[pos] = s;
        }
    }
    __syncthreads();
    if (tid < 8) { base[tid] = atomicAdd(&g_relcur[tid], cnt[tid]); cnt[tid] = 0; }
    __syncthreads();
    #pragma unroll
    for (int c = 0; c < 4; c++) {
        if (rloc[c] >= 0) {
            int posr = base[rloc[c]] + atomicAdd(&cnt[rloc[c]], 1);
            g_edpos[posr] = dloc[c];
            g_srcr[posr]  = sloc[c];
            g_nidr[posr]  = nloc[c];
        }
    }
}

// ---------------- kernel 4: mma.sync bf16 score, work-stealing chunks -------
// Blocks grab relation-aligned 9-tile chunks via atomic; quads split a chunk
// 3 tiles each. Weight loads are coalesced copies from pre-packed globals.
// Epilogue uses a*lrelu(t) = a*t + (-0.8a)*min(t,0).
// SMEM (dynamic):
//   Wp0  [4096] u32                        : 0     .. 16384
//   Wp1  [4096] u32                        : 16384 .. 32768
//   A    [3 quads][2 mats][32 rows][36]    : 32768 .. 60416
//   bsum [128] f32                         : 60416 .. 60928
//   at2  [128] float2                      : 60928 .. 61952
#define OFF_WP0 0
#define OFF_WP1 16384
#define OFF_A   32768
#define OFF_B   60416
#define OFF_AT  60928
#define SMEM_SCORE_BYTES 61952

extern "C" __global__ void __launch_bounds__(384, 2)
k_score(const float* __restrict__ feat, const float* __restrict__ qual)
{
    extern __shared__ unsigned char sm[];
    u32*    wp0  = (u32*)(sm + OFF_WP0);
    u32*    wp1  = (u32*)(sm + OFF_WP1);
    float*  bsum = (float*)(sm + OFF_B);
    float2* at2  = (float2*)(sm + OFF_AT);
    __shared__ int s_chunk;

    const int tid  = threadIdx.x;
    const int wid  = tid >> 5, lane = tid & 31;
    const int qid  = wid >> 2;           // 0..2
    const int wq   = wid & 3;            // head owned by this warp
    const int qtid = tid & 127;          // thread id within quad
    const int g = lane >> 2, tg = lane & 3;
    const int grp = qtid >> 3;           // 0..15 (gather row-group)
    const int gj  = qtid & 7;            // 16B slot within row-half

    u32* As = (u32*)(sm + OFF_A) + qid * 2304;    // 2 mats x 32 x 36 u32

    int woff[9], roff[9], choff[9];
    #pragma unroll
    for (int i = 0; i < 9; i++) {
        woff[i] = g_woff[i]; roff[i] = g_roff[i]; choff[i] = g_choff[i];
    }
    const int nch = choff[8];
    int cur_rel = -1;

    for (;;) {
        if (tid == 0) s_chunk = atomicAdd(&g_chunkcur, 1);
        __syncthreads();                  // broadcast chunk; all quads idle
        const int ch = s_chunk;
        if (ch >= nch) break;

        int r = 0;
        while (ch >= choff[r + 1]) r++;

        if (r != cur_rel) {
            // coalesced copy of pre-packed weights + bias/attn
            const uint4* s0 = (const uint4*)&g_wpk[r][0][0];
            const uint4* s1 = (const uint4*)&g_wpk[r][1][0];
            uint4* d0 = (uint4*)wp0;
            uint4* d1 = (uint4*)wp1;
            for (int i = tid; i < 1024; i += 384) { d0[i] = s0[i]; d1[i] = s1[i]; }
            if (tid < 128) {
                bsum[tid] = g_bs[r][tid];
                at2[tid]  = g_at[r][tid];
            }
            cur_rel = r;
            __syncthreads();
        }

        const int relend = roff[r + 1];
        const int rbase  = roff[r] - woff[r] * 32;
        const int tlo = woff[r] + (ch - choff[r]) * CH;
        const int thi = min(tlo + CH, woff[r + 1]);

        // prologue ids for this quad's first tile
        int ids_s = 0, ids_n = 0;
        {
            int est = rbase + (tlo + qid) * 32;
            int pos = max(min(est + lane, relend - 1), 0);
            ids_s = g_srcr[pos];
            ids_n = g_nidr[pos];
        }

        for (int wt = tlo + qid; wt < thi; wt += NQUAD) {
            const int estart = rbase + wt * 32;

            // ---- gather both mats: 8 independent LDG.128/thread ----
            #pragma unroll
            for (int mat = 0; mat < 2; mat++) {
                const float* basep = mat == 0 ? feat : qual;
                #pragma unroll
                for (int i = 0; i < 4; i++) {
                    int rhl = i * 16 + grp;
                    int row = rhl >> 1, h = rhl & 1;
                    int nd = __shfl_sync(0xffffffffu,
                                         mat == 0 ? ids_s : ids_n, row);
                    float4 v = *(const float4*)(basep + (size_t)nd * 64
                                                + h * 32 + gj * 4);
                    uint2 t;
                    t.x = bf2(v.x, v.y);
                    t.y = bf2(v.z, v.w);
                    *(uint2*)(As + mat * 1152 + row * 36 + h * 16 + gj * 2) = t;
                }
            }

            // ---- prefetch next tile's ids (hidden under MMA) ----
            int ids_s2, ids_n2;
            {
                int est2 = rbase + (wt + NQUAD) * 32;
                int pos = max(min(est2 + lane, relend - 1), 0);
                ids_s2 = g_srcr[pos];
                ids_n2 = g_nidr[pos];
            }

            barq(1 + qid);

            // ---- MMAs: 2 mats x 4 ks x (2 m-tiles x 4 n-tiles) ----
            float d[2][4][4];
            #pragma unroll
            for (int mt = 0; mt < 2; mt++)
                #pragma unroll
                for (int nt = 0; nt < 4; nt++)
                    #pragma unroll
                    for (int j = 0; j < 4; j++) d[mt][nt][j] = 0.f;

            #pragma unroll
            for (int mat = 0; mat < 2; mat++) {
                const uint2* wp = (const uint2*)(mat == 0 ? wp0 : wp1);
                const u32* Am = As + mat * 1152;
                #pragma unroll
                for (int ks = 0; ks < 4; ks++) {
                    int c0 = ks * 8 + tg;
                    u32 a[2][4];
                    #pragma unroll
                    for (int mt = 0; mt < 2; mt++) {
                        int rb = 16 * mt;
                        a[mt][0] = Am[(rb + g) * 36 + c0];
                        a[mt][1] = Am[(rb + g + 8) * 36 + c0];
                        a[mt][2] = Am[(rb + g) * 36 + c0 + 4];
                        a[mt][3] = Am[(rb + g + 8) * 36 + c0 + 4];
                    }
                    #pragma unroll
                    for (int ntl = 0; ntl < 4; ntl++) {
                        int nt = 4 * wq + ntl;
                        uint2 b = wp[(ks * 16 + nt) * 32 + lane];
                        #pragma unroll
                        for (int mt = 0; mt < 2; mt++)
                            mma16(d[mt][ntl], a[mt][0], a[mt][1],
                                  a[mt][2], a[mt][3], b.x, b.y);
                    }
                }
            }
            barq(1 + qid);   // slab consumed; safe to overwrite next iter

            // ---- epilogue: a*lrelu(t) = a*t + (-0.8a)*min(t,0) ----
            #pragma unroll
            for (int mt = 0; mt < 2; mt++) {
                float slo = 0.f, shi = 0.f;
                #pragma unroll
                for (int ntl = 0; ntl < 4; ntl++) {
                    int c = 8 * (4 * wq + ntl) + 2 * tg;
                    float b0 = bsum[c], b1 = bsum[c + 1];
                    float2 a0 = at2[c], a1 = at2[c + 1];
                    float t0 = d[mt][ntl][0] + b0;
                    float t1 = d[mt][ntl][1] + b1;
                    float t2 = d[mt][ntl][2] + b0;
                    float t3 = d[mt][ntl][3] + b1;
                    slo = fmaf(a0.x, t0, fmaf(a0.y, fminf(t0, 0.f), slo));
                    slo = fmaf(a1.x, t1, fmaf(a1.y, fminf(t1, 0.f), slo));
                    shi = fmaf(a0.x, t2, fmaf(a0.y, fminf(t2, 0.f), shi));
                    shi = fmaf(a1.x, t3, fmaf(a1.y, fminf(t3, 0.f), shi));
                }
                #pragma unroll
                for (int off = 1; off <= 2; off <<= 1) {
                    slo += __shfl_xor_sync(0xffffffffu, slo, off);
                    shi += __shfl_xor_sync(0xffffffffu, shi, off);
                }
                if (tg == 0) {
                    int plo = estart + 16 * mt + g;
                    if (plo < relend) {
                        int dp = g_edpos[plo];
                        g_p[dp * 4 + wq] = expf(slo);
                    }
                    int phi = estart + 16 * mt + g + 8;
                    if (phi < relend) {
                        int dp = g_edpos[phi];
                        g_p[dp * 4 + wq] = expf(shi);
                    }
                }
            }

            ids_s = ids_s2; ids_n = ids_n2;
        }
    }
}

// ---------------- kernel 5: per-node CSR aggregation (streaming) ------------
extern "C" __global__ void __launch_bounds__(256)
k_agg(const float* __restrict__ feat, float* __restrict__ out)
{
    const int gid = blockIdx.x * 256 + threadIdx.x;
    if (gid < NB_D) g_agg_f[gid] = 0;            // reset scan flags for replay

    const int n = gid >> 5;                      // node id (warp per node)
    const int lane = threadIdx.x & 31;
    if (n >= N_NODES) return;
    if (lane == 0) g_dstcnt[n] = 0;              // reset histogram for replay

    const int beg = g_rowoff[n], end = g_rowoff[n + 1];

    float a00 = 0.f, a01 = 0.f, a10 = 0.f, a11 = 0.f;
    float a20 = 0.f, a21 = 0.f, a30 = 0.f, a31 = 0.f;
    float d0 = 0.f, d1 = 0.f, d2 = 0.f, d3 = 0.f;

    int s = (beg < end) ? g_srcd[beg] : 0;
    for (int i = beg; i < end; i++) {
        int s_n = (i + 1 < end) ? g_srcd[i + 1] : 0;
        float4 p = ((const float4*)g_p)[i];
        float2 f = *(const float2*)&feat[(size_t)s * 64 + 2 * lane];
        a00 += p.x * f.x; a01 += p.x * f.y; d0 += p.x;
        a10 += p.y * f.x; a11 += p.y * f.y; d1 += p.y;
        a20 += p.z * f.x; a21 += p.z * f.y; d2 += p.z;
        a30 += p.w * f.x; a31 += p.w * f.y; d3 += p.w;
        s = s_n;
    }

    float i0 = d0 > 0.f ? __frcp_rn(d0) : 0.f;
    float i1 = d1 > 0.f ? __frcp_rn(d1) : 0.f;
    float i2 = d2 > 0.f ? __frcp_rn(d2) : 0.f;
    float i3 = d3 > 0.f ? __frcp_rn(d3) : 0.f;

    float* o = out + (size_t)n * 256 + 2 * lane;
    *(float2*)(o)       = make_float2(a00 * i0, a01 * i0);
    *(float2*)(o + 64)  = make_float2(a10 * i1, a11 * i1);
    *(float2*)(o + 128) = make_float2(a20 * i2, a21 * i2);
    *(float2*)(o + 192) = make_float2(a30 * i3, a31 * i3);
}

// ---------------- launcher --------------------------------------------------
extern "C" void kernel_launch(void* const* d_in, const int* in_sizes, int n_in,
                              void* d_out, int out_size)
{
    const float* feat  = (const float*)d_in[0];
    const float* qual  = (const float*)d_in[1];
    const float* Wsrc  = (const float*)d_in[2];
    const float* Bsrc  = (const float*)d_in[3];
    const float* Wqual = (const float*)d_in[4];
    const float* Bqual = (const float*)d_in[5];
    const float* attn  = (const float*)d_in[6];
    const void*  src   = d_in[7];
    const void*  dst   = d_in[8];
    const void*  rt    = d_in[9];
    const void*  nid   = d_in[10];
    float* out = (float*)d_out;

    static bool attr_set = false;
    if (!attr_set) {
        cudaFuncSetAttribute(k_score, cudaFuncAttributeMaxDynamicSharedMemorySize,
                             SMEM_SCORE_BYTES);
        attr_set = true;
    }

    k_hist<<<NBLK_HIST, 256>>>(rt, dst, Wsrc, Bsrc, Wqual, Bqual, attn);  // #1
    k_scan<<<NB_D, 1024>>>();                                             // #2
    k_scatter<<<NBLK_HIST, 256>>>(rt, dst, src, nid);                     // #3
    k_score<<<296, 384, SMEM_SCORE_BYTES>>>(feat, qual);                  // #4
    k_agg<<<(N_NODES * 32 + 255) / 256, 256>>>(feat, out);                // #5
}

// round 16
// speedup vs baseline: 1.1244x; 1.1244x over previous
#include <cuda_runtime.h>
#include <cstdint>

#define N_NODES   100000
#define N_REL     8
#define IN_FEATS  64
#define HD        128
#define N_EDGES   800000
#define NEG_SLOPE 0.2f

#define EPB_HIST  1024
#define NBLK_HIST ((N_EDGES + EPB_HIST - 1) / EPB_HIST)   // 782
#define NB_D      ((N_NODES + 1023) / 1024)               // 98

#define NQUAD 3                 // warp quads per 384-thread block

typedef unsigned long long u64;
typedef unsigned int u32;

// ---------------- scratch ---------------------------------------------------
__device__ float g_p[N_EDGES * 4];       // exp(score), stored in DST order
__device__ int   g_edpos[N_EDGES];       // dst-order slot of each rel-sorted edge
__device__ int   g_srcr[N_EDGES];        // src node id, relation order
__device__ int   g_nidr[N_EDGES];        // nid node id, relation order
__device__ int   g_srcd[N_EDGES];        // src node id, dst order
__device__ int   g_relcnt[8];            // zero-init; re-zeroed by k_scan
__device__ int   g_relcur[8];
__device__ int   g_roff[9];
__device__ int   g_woff[9];              // 32-edge tile offsets per relation
__device__ int   g_dstcnt[N_NODES];      // zero-init; re-zeroed by k_agg
__device__ int   g_rowoff[N_NODES + 1];
__device__ int   g_dstcur[N_NODES];
__device__ int   g_agg_v[NB_D];
__device__ int   g_agg_f[NB_D];          // zero-init; re-zeroed by k_agg
__device__ u32   g_wpk[8][2][4096];      // pre-packed bf16 weight fragments
__device__ float g_bs[8][128];           // bias sums
__device__ float2 g_at[8][128];          // (attn, -0.8*attn)

// ---------------- helpers ---------------------------------------------------
__device__ __forceinline__ long long ldidx(const void* p, int i, int is32) {
    return is32 ? (long long)((const int*)p)[i] : ((const long long*)p)[i];
}
// pack two floats -> bf16x2 (lo in low 16 bits)
__device__ __forceinline__ u32 bf2(float lo, float hi) {
    u32 r; asm("cvt.rn.bf16x2.f32 %0, %1, %2;" : "=r"(r) : "f"(hi), "f"(lo)); return r;
}
__device__ __forceinline__ void mma16(float* d, u32 a0, u32 a1, u32 a2, u32 a3,
                                      u32 b0, u32 b1) {
    asm volatile(
        "mma.sync.aligned.m16n8k16.row.col.f32.bf16.bf16.f32 "
        "{%0,%1,%2,%3}, {%4,%5,%6,%7}, {%8,%9}, {%0,%1,%2,%3};"
        : "+f"(d[0]), "+f"(d[1]), "+f"(d[2]), "+f"(d[3])
        : "r"(a0), "r"(a1), "r"(a2), "r"(a3), "r"(b0), "r"(b1));
}
__device__ __forceinline__ void barq(int id) {
    asm volatile("bar.sync %0, 128;" :: "r"(id) : "memory");
}
__device__ __forceinline__ int detect32(const void* p) {
    const long long* q = (const long long*)p;
    int bad = 0;
    #pragma unroll
    for (int j = 0; j < 16; j++) {
        long long v = q[j];
        if (v < 0 || v >= N_NODES) bad = 1;
    }
    return bad;
}

// ---------------- kernel 1: histogram + one-time weight pre-pack ------------
__global__ void k_hist(const void* __restrict__ rtp, const void* __restrict__ dstp,
                       const float* __restrict__ Wsrc, const float* __restrict__ Bsrc,
                       const float* __restrict__ Wqual, const float* __restrict__ Bqual,
                       const float* __restrict__ attn) {
    __shared__ int cnt[8];
    __shared__ int s_is32;
    int tid = threadIdx.x;
    if (tid < 8) cnt[tid] = 0;
    if (tid == 0) s_is32 = detect32(dstp);
    __syncthreads();
    const int is32 = s_is32;

    // blocks 0..127: pack weight fragments (one thread per fragment slot)
    int gidx = blockIdx.x * 256 + tid;
    if (gidx < 8 * 4096) {
        int idx = gidx & 4095;
        int r   = gidx >> 12;
        int half = idx & 1;
        int ln   = (idx >> 1) & 31;
        int nt   = (idx >> 6) & 15;
        int ks   = idx >> 10;
        int k = 16 * ks + 2 * (ln & 3) + 8 * half;
        int n = 8 * nt + (ln >> 2);
        const float* w0 = &Wsrc [(r * 64 + k) * 128 + n];
        const float* w1 = &Wqual[(r * 64 + k) * 128 + n];
        g_wpk[r][0][idx] = bf2(w0[0], w0[128]);
        g_wpk[r][1][idx] = bf2(w1[0], w1[128]);
    }
    if (gidx < 8 * 128) {
        int r = gidx >> 7, c = gidx & 127;
        g_bs[r][c] = Bsrc[r * 128 + c] + Bqual[r * 128 + c];
        float a = attn[r * 128 + c];
        g_at[r][c] = make_float2(a, -0.8f * a);
    }

    int base = blockIdx.x * EPB_HIST;
    for (int i = tid; i < EPB_HIST; i += 256) {
        int e = base + i;
        if (e < N_EDGES) {
            atomicAdd(&cnt[(int)ldidx(rtp, e, is32)], 1);
            atomicAdd(&g_dstcnt[(int)ldidx(dstp, e, is32)], 1);
        }
    }
    __syncthreads();
    if (tid < 8) atomicAdd(&g_relcnt[tid], cnt[tid]);
}

// ---------------- kernel 2: single-launch dst scan (decoupled lookback) -----
__global__ void __launch_bounds__(1024) k_scan() {
    __shared__ int ws[32];
    __shared__ int s_pred;
    int t = threadIdx.x, b = blockIdx.x;
    int i = b * 1024 + t;
    int v = (i < N_NODES) ? g_dstcnt[i] : 0;
    int lane = t & 31, w = t >> 5;
    int x = v;
    #pragma unroll
    for (int o = 1; o < 32; o <<= 1) {
        int y = __shfl_up_sync(0xffffffffu, x, o);
        if (lane >= o) x += y;
    }
    if (lane == 31) ws[w] = x;
    __syncthreads();
    if (t < 32) {
        int y = ws[t];
        #pragma unroll
        for (int o = 1; o < 32; o <<= 1) {
            int z = __shfl_up_sync(0xffffffffu, y, o);
            if (t >= o) y += z;
        }
        ws[t] = y;
    }
    __syncthreads();
    int excl = x - v + (w ? ws[w - 1] : 0);
    int btot = ws[31];
    if (t == 0) {
        s_pred = 0;
        g_agg_v[b] = btot;
        __threadfence();
        atomicExch(&g_agg_f[b], 1);
    }
    __syncthreads();
    if (t < b) {
        while (atomicAdd(&g_agg_f[t], 0) == 0) {}
        atomicAdd(&s_pred, atomicAdd(&g_agg_v[t], 0));
    }
    __syncthreads();
    int base = s_pred;
    if (i < N_NODES) {
        int val = base + excl;
        g_rowoff[i] = val;
        g_dstcur[i] = val;
    }
    if (b == 0 && t == 0) {
        int ro = 0, wo = 0;
        for (int r = 0; r < 8; r++) {
            int c = g_relcnt[r];
            g_roff[r] = ro; g_relcur[r] = ro; g_woff[r] = wo;
            ro += c; wo += (c + 31) / 32;          // 32-edge tiles
            g_relcnt[r] = 0;
        }
        g_roff[8] = ro; g_woff[8] = wo;
        g_rowoff[N_NODES] = N_EDGES;
    }
}

// ---------------- kernel 3: fused scatter (rel ids + dst slots) -------------
__global__ void k_scatter(const void* __restrict__ rtp, const void* __restrict__ dstp,
                          const void* __restrict__ srcp, const void* __restrict__ nidp) {
    __shared__ int cnt[8], base[8];
    __shared__ int s_is32;
    int tid = threadIdx.x;
    if (tid < 8) cnt[tid] = 0;
    if (tid == 0) s_is32 = detect32(dstp);
    __syncthreads();
    const int is32 = s_is32;
    int b0 = blockIdx.x * EPB_HIST;
    int rloc[4], dloc[4], sloc[4], nloc[4];
    #pragma unroll
    for (int c = 0; c < 4; c++) {
        int e = b0 + c * 256 + tid;
        rloc[c] = -1;
        if (e < N_EDGES) {
            rloc[c] = (int)ldidx(rtp, e, is32);
            atomicAdd(&cnt[rloc[c]], 1);
            int d = (int)ldidx(dstp, e, is32);
            int s = (int)ldidx(srcp, e, is32);
            int q = (int)ldidx(nidp, e, is32);
            int pos = atomicAdd(&g_dstcur[d], 1);
            dloc[c] = pos; sloc[c] = s; nloc[c] = q;
            g_srcd[pos] = s;
        }
    }
    __syncthreads();
    if (tid < 8) { base[tid] = atomicAdd(&g_relcur[tid], cnt[tid]); cnt[tid] = 0; }
    __syncthreads();
    #pragma unroll
    for (int c = 0; c < 4; c++) {
        if (rloc[c] >= 0) {
            int posr = base[rloc[c]] + atomicAdd(&cnt[rloc[c]], 1);
            g_edpos[posr] = dloc[c];
            g_srcr[posr]  = sloc[c];
            g_nidr[posr]  = nloc[c];
        }
    }
}

// ---------------- kernel 4: mma.sync bf16 score, QUAD tiles (static) --------
// R14 static partition + pre-packed weights (coalesced copy) + cheap epilogue.
// SMEM (dynamic):
//   Wp0  [4096] u32                        : 0     .. 16384
//   Wp1  [4096] u32                        : 16384 .. 32768
//   A    [3 quads][2 mats][32 rows][36]    : 32768 .. 60416
//   bsum [128] f32                         : 60416 .. 60928
//   at2  [128] float2                      : 60928 .. 61952
#define OFF_WP0 0
#define OFF_WP1 16384
#define OFF_A   32768
#define OFF_B   60416
#define OFF_AT  60928
#define SMEM_SCORE_BYTES 61952

extern "C" __global__ void __launch_bounds__(384, 2)
k_score(const float* __restrict__ feat, const float* __restrict__ qual)
{
    extern __shared__ unsigned char sm[];
    u32*    wp0  = (u32*)(sm + OFF_WP0);
    u32*    wp1  = (u32*)(sm + OFF_WP1);
    float*  bsum = (float*)(sm + OFF_B);
    float2* at2  = (float2*)(sm + OFF_AT);

    const int tid  = threadIdx.x;
    const int wid  = tid >> 5, lane = tid & 31;
    const int qid  = wid >> 2;           // 0..2
    const int wq   = wid & 3;            // head owned by this warp
    const int qtid = tid & 127;          // thread id within quad
    const int g = lane >> 2, tg = lane & 3;
    const int grp = qtid >> 3;           // 0..15 (gather row-group)
    const int gj  = qtid & 7;            // 16B slot within row-half

    u32* As = (u32*)(sm + OFF_A) + qid * 2304;    // 2 mats x 32 x 36 u32

    int woff[9], roff[9];
    #pragma unroll
    for (int i = 0; i < 9; i++) { woff[i] = g_woff[i]; roff[i] = g_roff[i]; }
    const int totalw = woff[8];
    const int wtpb = (totalw + gridDim.x - 1) / gridDim.x;
    const int wt0 = blockIdx.x * wtpb;
    const int wt1 = min(wt0 + wtpb, totalw);
    if (wt0 >= wt1) return;

    for (int r = 0; r < 8; r++) {
        const int lo = max(wt0, woff[r]);
        const int hi = min(wt1, woff[r + 1]);
        if (lo >= hi) continue;

        // ---- coalesced copy of pre-packed weights + bias/attn ----
        __syncthreads();
        {
            const uint4* s0 = (const uint4*)&g_wpk[r][0][0];
            const uint4* s1 = (const uint4*)&g_wpk[r][1][0];
            uint4* d0 = (uint4*)wp0;
            uint4* d1 = (uint4*)wp1;
            for (int i = tid; i < 1024; i += 384) { d0[i] = s0[i]; d1[i] = s1[i]; }
            if (tid < 128) {
                bsum[tid] = g_bs[r][tid];
                at2[tid]  = g_at[r][tid];
            }
        }
        __syncthreads();

        const int relend = roff[r + 1];
        const int rbase  = roff[r] - woff[r] * 32;

        // prologue ids for this quad's first tile
        int ids_s, ids_n;
        {
            int est = rbase + (lo + qid) * 32;
            int pos = max(min(est + lane, relend - 1), 0);
            ids_s = g_srcr[pos];
            ids_n = g_nidr[pos];
        }

        for (int wt = lo + qid; wt < hi; wt += NQUAD) {
            const int estart = rbase + wt * 32;

            // ---- gather both mats: 8 independent LDG.128/thread ----
            #pragma unroll
            for (int mat = 0; mat < 2; mat++) {
                const float* basep = mat == 0 ? feat : qual;
                #pragma unroll
                for (int i = 0; i < 4; i++) {
                    int rhl = i * 16 + grp;
                    int row = rhl >> 1, h = rhl & 1;
                    int nd = __shfl_sync(0xffffffffu,
                                         mat == 0 ? ids_s : ids_n, row);
                    float4 v = *(const float4*)(basep + (size_t)nd * 64
                                                + h * 32 + gj * 4);
                    uint2 t;
                    t.x = bf2(v.x, v.y);
                    t.y = bf2(v.z, v.w);
                    *(uint2*)(As + mat * 1152 + row * 36 + h * 16 + gj * 2) = t;
                }
            }

            // ---- prefetch next tile's ids (hidden under MMA) ----
            int ids_s2, ids_n2;
            {
                int est2 = rbase + (wt + NQUAD) * 32;
                int pos = max(min(est2 + lane, relend - 1), 0);
                ids_s2 = g_srcr[pos];
                ids_n2 = g_nidr[pos];
            }

            barq(1 + qid);

            // ---- MMAs: 2 mats x 4 ks x (2 m-tiles x 4 n-tiles) ----
            float d[2][4][4];
            #pragma unroll
            for (int mt = 0; mt < 2; mt++)
                #pragma unroll
                for (int nt = 0; nt < 4; nt++)
                    #pragma unroll
                    for (int j = 0; j < 4; j++) d[mt][nt][j] = 0.f;

            #pragma unroll
            for (int mat = 0; mat < 2; mat++) {
                const uint2* wp = (const uint2*)(mat == 0 ? wp0 : wp1);
                const u32* Am = As + mat * 1152;
                #pragma unroll
                for (int ks = 0; ks < 4; ks++) {
                    int c0 = ks * 8 + tg;
                    u32 a[2][4];
                    #pragma unroll
                    for (int mt = 0; mt < 2; mt++) {
                        int rb = 16 * mt;
                        a[mt][0] = Am[(rb + g) * 36 + c0];
                        a[mt][1] = Am[(rb + g + 8) * 36 + c0];
                        a[mt][2] = Am[(rb + g) * 36 + c0 + 4];
                        a[mt][3] = Am[(rb + g + 8) * 36 + c0 + 4];
                    }
                    #pragma unroll
                    for (int ntl = 0; ntl < 4; ntl++) {
                        int nt = 4 * wq + ntl;
                        uint2 b = wp[(ks * 16 + nt) * 32 + lane];
                        #pragma unroll
                        for (int mt = 0; mt < 2; mt++)
                            mma16(d[mt][ntl], a[mt][0], a[mt][1],
                                  a[mt][2], a[mt][3], b.x, b.y);
                    }
                }
            }
            barq(1 + qid);   // slab consumed; safe to overwrite next iter

            // ---- epilogue: a*lrelu(t) = a*t + (-0.8a)*min(t,0) ----
            #pragma unroll
            for (int mt = 0; mt < 2; mt++) {
                float slo = 0.f, shi = 0.f;
                #pragma unroll
                for (int ntl = 0; ntl < 4; ntl++) {
                    int c = 8 * (4 * wq + ntl) + 2 * tg;
                    float b0 = bsum[c], b1 = bsum[c + 1];
                    float2 a0 = at2[c], a1 = at2[c + 1];
                    float t0 = d[mt][ntl][0] + b0;
                    float t1 = d[mt][ntl][1] + b1;
                    float t2 = d[mt][ntl][2] + b0;
                    float t3 = d[mt][ntl][3] + b1;
                    slo = fmaf(a0.x, t0, fmaf(a0.y, fminf(t0, 0.f), slo));
                    slo = fmaf(a1.x, t1, fmaf(a1.y, fminf(t1, 0.f), slo));
                    shi = fmaf(a0.x, t2, fmaf(a0.y, fminf(t2, 0.f), shi));
                    shi = fmaf(a1.x, t3, fmaf(a1.y, fminf(t3, 0.f), shi));
                }
                #pragma unroll
                for (int off = 1; off <= 2; off <<= 1) {
                    slo += __shfl_xor_sync(0xffffffffu, slo, off);
                    shi += __shfl_xor_sync(0xffffffffu, shi, off);
                }
                if (tg == 0) {
                    int plo = estart + 16 * mt + g;
                    if (plo < relend) {
                        int dp = g_edpos[plo];
                        g_p[dp * 4 + wq] = expf(slo);
                    }
                    int phi = estart + 16 * mt + g + 8;
                    if (phi < relend) {
                        int dp = g_edpos[phi];
                        g_p[dp * 4 + wq] = expf(shi);
                    }
                }
            }

            ids_s = ids_s2; ids_n = ids_n2;
        }
    }
}

// ---------------- kernel 5: per-node CSR aggregation (streaming) ------------
extern "C" __global__ void __launch_bounds__(256)
k_agg(const float* __restrict__ feat, float* __restrict__ out)
{
    const int gid = blockIdx.x * 256 + threadIdx.x;
    if (gid < NB_D) g_agg_f[gid] = 0;            // reset scan flags for replay

    const int n = gid >> 5;                      // node id (warp per node)
    const int lane = threadIdx.x & 31;
    if (n >= N_NODES) return;
    if (lane == 0) g_dstcnt[n] = 0;              // reset histogram for replay

    const int beg = g_rowoff[n], end = g_rowoff[n + 1];

    float a00 = 0.f, a01 = 0.f, a10 = 0.f, a11 = 0.f;
    float a20 = 0.f, a21 = 0.f, a30 = 0.f, a31 = 0.f;
    float d0 = 0.f, d1 = 0.f, d2 = 0.f, d3 = 0.f;

    int s = (beg < end) ? g_srcd[beg] : 0;
    for (int i = beg; i < end; i++) {
        int s_n = (i + 1 < end) ? g_srcd[i + 1] : 0;
        float4 p = ((const float4*)g_p)[i];
        float2 f = *(const float2*)&feat[(size_t)s * 64 + 2 * lane];
        a00 += p.x * f.x; a01 += p.x * f.y; d0 += p.x;
        a10 += p.y * f.x; a11 += p.y * f.y; d1 += p.y;
        a20 += p.z * f.x; a21 += p.z * f.y; d2 += p.z;
        a30 += p.w * f.x; a31 += p.w * f.y; d3 += p.w;
        s = s_n;
    }

    float i0 = d0 > 0.f ? __frcp_rn(d0) : 0.f;
    float i1 = d1 > 0.f ? __frcp_rn(d1) : 0.f;
    float i2 = d2 > 0.f ? __frcp_rn(d2) : 0.f;
    float i3 = d3 > 0.f ? __frcp_rn(d3) : 0.f;

    float* o = out + (size_t)n * 256 + 2 * lane;
    *(float2*)(o)       = make_float2(a00 * i0, a01 * i0);
    *(float2*)(o + 64)  = make_float2(a10 * i1, a11 * i1);
    *(float2*)(o + 128) = make_float2(a20 * i2, a21 * i2);
    *(float2*)(o + 192) = make_float2(a30 * i3, a31 * i3);
}

// ---------------- launcher --------------------------------------------------
extern "C" void kernel_launch(void* const* d_in, const int* in_sizes, int n_in,
                              void* d_out, int out_size)
{
    const float* feat  = (const float*)d_in[0];
    const float* qual  = (const float*)d_in[1];
    const float* Wsrc  = (const float*)d_in[2];
    const float* Bsrc  = (const float*)d_in[3];
    const float* Wqual = (const float*)d_in[4];
    const float* Bqual = (const float*)d_in[5];
    const float* attn  = (const float*)d_in[6];
    const void*  src   = d_in[7];
    const void*  dst   = d_in[8];
    const void*  rt    = d_in[9];
    const void*  nid   = d_in[10];
    float* out = (float*)d_out;

    static bool attr_set = false;
    if (!attr_set) {
        cudaFuncSetAttribute(k_score, cudaFuncAttributeMaxDynamicSharedMemorySize,
                             SMEM_SCORE_BYTES);
        attr_set = true;
    }

    k_hist<<<NBLK_HIST, 256>>>(rt, dst, Wsrc, Bsrc, Wqual, Bqual, attn);  // #1
    k_scan<<<NB_D, 1024>>>();                                             // #2
    k_scatter<<<NBLK_HIST, 256>>>(rt, dst, src, nid);                     // #3
    k_score<<<296, 384, SMEM_SCORE_BYTES>>>(feat, qual);                  // #4
    k_agg<<<(N_NODES * 32 + 255) / 256, 256>>>(feat, out);                // #5
}